// round 16
// baseline (speedup 1.0000x reference)
#include <cuda_runtime.h>
#include <math.h>

#define NNODE 32768
#define NEDGE 524288
#define EPSF  1e-15f

// ---------------- int scratch offsets ----------------
#define IO_DCNT  0LL
#define IO_SCNT  (IO_DCNT+32768)
#define IO_DOFF  (IO_SCNT+32768)
#define IO_SOFF  (IO_DOFF+32772)
#define IO_DCUR  (IO_SOFF+32772)
#define IO_SCUR  (IO_DCUR+32768)
#define IO_DLIST (IO_SCUR+32768)
#define IO_SLIST (IO_DLIST+524288)
#define IO_PART  (IO_SLIST+524288)
#define IO_PL1   (IO_PART+64)
#define IO_PL2   (IO_PL1+16384)
#define IO_PL3   (IO_PL2+8192)
#define IO_PO1   (IO_PL3+4096)
#define IO_PO2   (IO_PO1+16384)
#define IO_CM1   (IO_PO2+8192)
#define IO_CM2   (IO_CM1+32768)
#define I_TOT    (IO_CM2+32768)
__device__ int g_i[I_TOT];

// ---------------- float scratch offsets ----------------
#define OF_X0    0LL
#define OF_AGGB  (OF_X0+4194304)
#define OF_SBIG  (OF_AGGB+4194304)
#define OF_T1    (OF_SBIG+8388608)
#define OF_XD1   (OF_T1+8388608)
#define OF_OADJ1 (OF_XD1+2097152)
#define OF_SS1   (OF_OADJ1+4194304)
#define OF_XDS1  (OF_SS1+4194304)
#define OF_S2    (OF_XDS1+2097152)
#define OF_XD2   (OF_S2+2097152)
#define OF_T2    (OF_XD2+1048576)
#define OF_OADJ2 (OF_T2+2097152)
#define OF_SS2   (OF_OADJ2+1048576)
#define OF_XDS2  (OF_SS2+1048576)
#define OF_SXA   (OF_XDS2+1048576)
#define OF_SXB   (OF_SXA+2097152)
#define OF_SXC   (OF_SXB+2097152)
#define OF_SXD   (OF_SXC+1048576)
#define OF_SXE   (OF_SXD+1048576)
#define OF_SCORE (OF_SXE+524288)
#define OF_DEG   (OF_SCORE+32768)
#define OF_DP    (OF_DEG+32768)
#define OF_RS1   (OF_DP+16384)
#define OF_RS2   (OF_RS1+16384)
#define OF_SXS   (OF_RS2+8192)
#define OF_MEAN  (OF_SXS+16384)
#define OF_XG    (OF_MEAN+8192)
#define OF_SXR   (OF_XG+8192)
#define OF_ST    (OF_SXR+8192)
#define OF_PN    (OF_ST+256)
#define OF_SAGG  (OF_PN+16)
#define F_TOT    (OF_SAGG+2097152)
__device__ float g_f[F_TOT];

// ---------------- streams/events (static init) ----------------
static cudaStream_t g_sB = 0, g_sC = 0;
static cudaEvent_t  g_ev[8];
struct _StreamInit {
    _StreamInit(){
        cudaStreamCreateWithFlags(&g_sB, cudaStreamNonBlocking);
        cudaStreamCreateWithFlags(&g_sC, cudaStreamNonBlocking);
        for(int i=0;i<8;i++) cudaEventCreateWithFlags(&g_ev[i], cudaEventDisableTiming);
    }
};
static _StreamInit g_stream_init;

// ---------------- utility ----------------
__global__ void k_zerof(float* p, long long n){
    long long i=(long long)blockIdx.x*blockDim.x+threadIdx.x; if(i<n)p[i]=0.f;
}
__global__ void k_zeroi(long long base, long long n){
    long long i=(long long)blockIdx.x*blockDim.x+threadIdx.x; if(i<n)g_i[base+i]=0;
}
__global__ void k_fillneg(long long base, long long n){
    long long i=(long long)blockIdx.x*blockDim.x+threadIdx.x; if(i<n)g_i[base+i]=-1;
}

// ---------------- CSR build ----------------
__global__ void k_count(const int* __restrict__ src, const int* __restrict__ dst){
    int e=blockIdx.x*blockDim.x+threadIdx.x;
    if(e<NEDGE){ atomicAdd(&g_i[IO_DCNT+dst[e]],1); atomicAdd(&g_i[IO_SCNT+src[e]],1); }
}
__global__ void k_scan_blk(){
    int pass=blockIdx.y;
    long long cb = pass? IO_SCNT:IO_DCNT;
    long long ob = pass? IO_SOFF:IO_DOFF;
    int base = blockIdx.x*1024 + threadIdx.x*4;
    int4 v = *(const int4*)&g_i[cb+base];
    int s = v.x+v.y+v.z+v.w;
    int lane=threadIdx.x&31, wid=threadIdx.x>>5;
    int p=s;
    #pragma unroll
    for(int o=1;o<32;o<<=1){ int u=__shfl_up_sync(0xffffffffu,p,o); if(lane>=o)p+=u; }
    __shared__ int ws[8];
    if(lane==31) ws[wid]=p;
    __syncthreads();
    if(threadIdx.x<8){
        int u=ws[threadIdx.x];
        #pragma unroll
        for(int o=1;o<8;o<<=1){ int q=__shfl_up_sync(0xffu,u,o); if((int)threadIdx.x>=o)u+=q; }
        ws[threadIdx.x]=u;
    }
    __syncthreads();
    int excl = p - s + (wid? ws[wid-1]:0);
    int4 w4; w4.x=excl; w4.y=w4.x+v.x; w4.z=w4.y+v.y; w4.w=w4.z+v.z;
    *(int4*)&g_i[ob+base]=w4;
    if(threadIdx.x==255) g_i[IO_PART + pass*32 + blockIdx.x] = excl + s;
}
__global__ void k_scan_top(){
    int t=threadIdx.x; if(t>=64)return;
    int lane=t&31;
    int v=g_i[IO_PART+t];
    int p=v;
    #pragma unroll
    for(int o=1;o<32;o<<=1){ int u=__shfl_up_sync(0xffffffffu,p,o); if(lane>=o)p+=u; }
    g_i[IO_PART+t]=p-v;
}
__global__ void k_scan_add(){
    int pass=blockIdx.y;
    long long ob = pass? IO_SOFF:IO_DOFF;
    long long ub = pass? IO_SCUR:IO_DCUR;
    int add = g_i[IO_PART+pass*32+blockIdx.x];
    int base = blockIdx.x*1024 + threadIdx.x*4;
    int4 v=*(const int4*)&g_i[ob+base];
    v.x+=add; v.y+=add; v.z+=add; v.w+=add;
    *(int4*)&g_i[ob+base]=v;
    *(int4*)&g_i[ub+base]=v;
    if(blockIdx.x==0&&threadIdx.x==0) g_i[ob+NNODE]=NEDGE;
}
__global__ void k_fill(const int* __restrict__ src, const int* __restrict__ dst){
    int e=blockIdx.x*blockDim.x+threadIdx.x;
    if(e<NEDGE){
        int p=atomicAdd(&g_i[IO_DCUR+dst[e]],1); g_i[IO_DLIST+p]=e;
        int q=atomicAdd(&g_i[IO_SCUR+src[e]],1); g_i[IO_SLIST+q]=e;
    }
}
__global__ void k_sortl(){
    int v=blockIdx.x*blockDim.x+threadIdx.x;
    if(v>=2*NNODE)return;
    int which=v/NNODE, node=v%NNODE;
    long long ob=which?IO_SOFF:IO_DOFF, lb=which?IO_SLIST:IO_DLIST;
    int a=g_i[ob+node], b=g_i[ob+node+1];
    for(int i=a+1;i<b;i++){
        int key=g_i[lb+i]; int j=i-1;
        while(j>=a && g_i[lb+j]>key){ g_i[lb+j+1]=g_i[lb+j]; j--; }
        g_i[lb+j+1]=key;
    }
}
__global__ void k_deg1(float* deg){
    int v=blockIdx.x*blockDim.x+threadIdx.x;
    if(v<NNODE) deg[v]=(float)(g_i[IO_SOFF+v+1]-g_i[IO_SOFF+v]);
}

// ---------------- graph-conv aggregation (warp per node, float4) ----------------
__global__ void k_agg_w(const float* __restrict__ x, const int* __restrict__ permO,
                        const int* __restrict__ cmap, const int* __restrict__ src,
                        float* __restrict__ out, int nn){
    int gw=(blockIdx.x*blockDim.x+threadIdx.x)>>5;
    int lane=threadIdx.x&31;
    if(gw>=nn)return;
    int v=permO?permO[gw]:gw;
    int s0=g_i[IO_DOFF+v], s1=g_i[IO_DOFF+v+1];
    float4 acc=make_float4(0.f,0.f,0.f,0.f);
    for(int p=s0;p<s1;p++){
        int e=g_i[IO_DLIST+p];
        int sv=src[e];
        int r=cmap?cmap[sv]:sv;
        if(r>=0){
            float4 u=*(const float4*)&x[(long long)r*128+lane*4];
            acc.x+=u.x; acc.y+=u.y; acc.z+=u.z; acc.w+=u.w;
        }
    }
    *(float4*)&out[(long long)gw*128+lane*4]=acc;
}
__global__ void k_adjs_w(const float* __restrict__ s, const int* __restrict__ dst,
                         float* __restrict__ T){
    int gw=(blockIdx.x*blockDim.x+threadIdx.x)>>5;
    int lane=threadIdx.x&31;
    if(gw>=NNODE)return;
    int s0=g_i[IO_SOFF+gw], s1=g_i[IO_SOFF+gw+1];
    float4 a0=make_float4(0.f,0.f,0.f,0.f), a1=a0;
    for(int p=s0;p<s1;p++){
        int e=g_i[IO_SLIST+p];
        const float4* row=(const float4*)&s[(long long)dst[e]*256];
        float4 u0=row[lane], u1=row[lane+32];
        a0.x+=u0.x; a0.y+=u0.y; a0.z+=u0.z; a0.w+=u0.w;
        a1.x+=u1.x; a1.y+=u1.y; a1.z+=u1.z; a1.w+=u1.w;
    }
    float4* o=(float4*)&T[(long long)gw*256];
    o[lane]=a0; o[lane+32]=a1;
}

// ---------------- fp32 tiled GEMM (sparse branch + conv0) ----------------
template<bool TA, bool DUAL>
__global__ void k_gemm128(const float* __restrict__ A, const float* __restrict__ B,
                          const float* __restrict__ A2, const float* __restrict__ B2,
                          const float* __restrict__ bias, float* __restrict__ C,
                          int M, int N, int K,
                          long long sA, long long sB, long long sC,
                          int accum, int relu){
    __shared__ __align__(16) float As[16][132];
    __shared__ __align__(16) float Bs[16][68];
    A += (long long)blockIdx.z*sA; B += (long long)blockIdx.z*sB; C += (long long)blockIdx.z*sC;
    if(DUAL){ A2 += (long long)blockIdx.z*sA; B2 += (long long)blockIdx.z*sB; }
    int m0=blockIdx.y*128, n0=blockIdx.x*64;
    int t=threadIdx.x, ty=t>>4, tx=t&15;
    float acc[8][4];
    #pragma unroll
    for(int i=0;i<8;i++)
        #pragma unroll
        for(int j=0;j<4;j++) acc[i][j]=0.f;
    #pragma unroll 1
    for(int pass=0; pass<(DUAL?2:1); pass++){
        const float* Ap = pass? A2 : A;
        const float* Bp = pass? B2 : B;
        for(int k0=0;k0<K;k0+=16){
            if(TA){
                int kk=t>>4, m=(t&15)*8;
                const float* p = Ap + (long long)(k0+kk)*M + m0 + m;
                float4 v0=*(const float4*)p, v1=*(const float4*)(p+4);
                As[kk][m+0]=v0.x; As[kk][m+1]=v0.y; As[kk][m+2]=v0.z; As[kk][m+3]=v0.w;
                As[kk][m+4]=v1.x; As[kk][m+5]=v1.y; As[kk][m+6]=v1.z; As[kk][m+7]=v1.w;
            }else{
                int r=t>>1, c=(t&1)*8;
                const float* p = Ap + (long long)(m0+r)*K + k0 + c;
                float4 v0=*(const float4*)p, v1=*(const float4*)(p+4);
                As[c+0][r]=v0.x; As[c+1][r]=v0.y; As[c+2][r]=v0.z; As[c+3][r]=v0.w;
                As[c+4][r]=v1.x; As[c+5][r]=v1.y; As[c+6][r]=v1.z; As[c+7][r]=v1.w;
            }
            {
                int kk=t>>4, n=(t&15)*4;
                *(float4*)&Bs[kk][n]=*(const float4*)(Bp + (long long)(k0+kk)*N + n0 + n);
            }
            __syncthreads();
            #pragma unroll
            for(int kk=0;kk<16;kk++){
                float4 b4=*(const float4*)&Bs[kk][tx*4];
                float4 a0=*(const float4*)&As[kk][ty*8];
                float4 a1=*(const float4*)&As[kk][ty*8+4];
                acc[0][0]+=a0.x*b4.x; acc[0][1]+=a0.x*b4.y; acc[0][2]+=a0.x*b4.z; acc[0][3]+=a0.x*b4.w;
                acc[1][0]+=a0.y*b4.x; acc[1][1]+=a0.y*b4.y; acc[1][2]+=a0.y*b4.z; acc[1][3]+=a0.y*b4.w;
                acc[2][0]+=a0.z*b4.x; acc[2][1]+=a0.z*b4.y; acc[2][2]+=a0.z*b4.z; acc[2][3]+=a0.z*b4.w;
                acc[3][0]+=a0.w*b4.x; acc[3][1]+=a0.w*b4.y; acc[3][2]+=a0.w*b4.z; acc[3][3]+=a0.w*b4.w;
                acc[4][0]+=a1.x*b4.x; acc[4][1]+=a1.x*b4.y; acc[4][2]+=a1.x*b4.z; acc[4][3]+=a1.x*b4.w;
                acc[5][0]+=a1.y*b4.x; acc[5][1]+=a1.y*b4.y; acc[5][2]+=a1.y*b4.z; acc[5][3]+=a1.y*b4.w;
                acc[6][0]+=a1.z*b4.x; acc[6][1]+=a1.z*b4.y; acc[6][2]+=a1.z*b4.z; acc[6][3]+=a1.z*b4.w;
                acc[7][0]+=a1.w*b4.x; acc[7][1]+=a1.w*b4.y; acc[7][2]+=a1.w*b4.z; acc[7][3]+=a1.w*b4.w;
            }
            __syncthreads();
        }
    }
    float4 bb=make_float4(0.f,0.f,0.f,0.f);
    if(bias) bb=*(const float4*)(bias+n0+tx*4);
    #pragma unroll
    for(int i=0;i<8;i++){
        long long m=m0+ty*8+i;
        float4 v=make_float4(acc[i][0],acc[i][1],acc[i][2],acc[i][3]);
        float4* cp=(float4*)&C[m*N + n0 + tx*4];
        if(accum){ float4 o=*cp; v.x+=o.x; v.y+=o.y; v.z+=o.z; v.w+=o.w; }
        v.x+=bb.x; v.y+=bb.y; v.z+=bb.z; v.w+=bb.w;
        if(relu){ v.x=fmaxf(v.x,0.f); v.y=fmaxf(v.y,0.f); v.z=fmaxf(v.z,0.f); v.w=fmaxf(v.w,0.f); }
        *cp=v;
    }
}

// ---------------- tf32 tensor-core GEMM (static smem — proven) ----------------
__device__ __forceinline__ unsigned f2tf(float f){
    unsigned r;
    asm("cvt.rna.tf32.f32 %0, %1;" : "=r"(r) : "f"(f));
    return r;
}
template<bool TA, bool DUAL>
__global__ void k_gemm_tc(const float* __restrict__ A, const float* __restrict__ B,
                          const float* __restrict__ A2, const float* __restrict__ B2,
                          const float* __restrict__ bias, const float* __restrict__ rsA,
                          float* __restrict__ C,
                          int M, int N, int K,
                          long long sA, long long sB, long long sC, int relu){
    __shared__ __align__(16) unsigned As[4608];
    __shared__ __align__(16) unsigned Bs[2304];
    A += (long long)blockIdx.z*sA; B += (long long)blockIdx.z*sB; C += (long long)blockIdx.z*sC;
    if(DUAL){ A2 += (long long)blockIdx.z*sA; B2 += (long long)blockIdx.z*sB; }
    int m0=blockIdx.y*128, n0=blockIdx.x*64;
    int t=threadIdx.x, w=t>>5, lane=t&31;
    int grp=lane>>2, tig=lane&3;
    int m_w=(w&3)*32, n_w=(w>>2)*32;
    float c[2][4][4];
    #pragma unroll
    for(int a=0;a<2;a++)
        #pragma unroll
        for(int b=0;b<4;b++)
            #pragma unroll
            for(int q=0;q<4;q++) c[a][b][q]=0.f;
    #pragma unroll 1
    for(int pass=0; pass<(DUAL?2:1); pass++){
        const float* Ap = pass? A2 : A;
        const float* Bp = pass? B2 : B;
        #pragma unroll 1
        for(int k0=0;k0<K;k0+=32){
            #pragma unroll
            for(int p=0;p<4;p++){
                int idx=p*1024+t*4;
                if(TA){
                    int k=idx>>7, m=idx&127;
                    float4 v=*(const float4*)(Ap + (long long)(k0+k)*M + m0 + m);
                    unsigned* d=&As[k*136+m];
                    d[0]=f2tf(v.x); d[1]=f2tf(v.y); d[2]=f2tf(v.z); d[3]=f2tf(v.w);
                }else{
                    int m=idx>>5, k=idx&31;
                    float4 v=*(const float4*)(Ap + (long long)(m0+m)*K + k0 + k);
                    if(rsA && pass==0){
                        float sc=1.f/fmaxf(rsA[m0+m],1.f);
                        v.x*=sc; v.y*=sc; v.z*=sc; v.w*=sc;
                    }
                    unsigned* d=&As[m*36+k];
                    d[0]=f2tf(v.x); d[1]=f2tf(v.y); d[2]=f2tf(v.z); d[3]=f2tf(v.w);
                }
            }
            #pragma unroll
            for(int p=0;p<2;p++){
                int idx=p*1024+t*4;
                int kk=idx>>6, n=idx&63;
                float4 v=*(const float4*)(Bp + (long long)(k0+kk)*N + n0 + n);
                unsigned* d=&Bs[kk*72+n];
                d[0]=f2tf(v.x); d[1]=f2tf(v.y); d[2]=f2tf(v.z); d[3]=f2tf(v.w);
            }
            __syncthreads();
            #pragma unroll
            for(int k8=0;k8<32;k8+=8){
                unsigned af[2][4], bf[4][2];
                #pragma unroll
                for(int mi=0;mi<2;mi++){
                    int mm=m_w+mi*16+grp;
                    if(TA){
                        af[mi][0]=As[(k8+tig)*136+mm];
                        af[mi][1]=As[(k8+tig)*136+mm+8];
                        af[mi][2]=As[(k8+tig+4)*136+mm];
                        af[mi][3]=As[(k8+tig+4)*136+mm+8];
                    }else{
                        af[mi][0]=As[mm*36+k8+tig];
                        af[mi][1]=As[(mm+8)*36+k8+tig];
                        af[mi][2]=As[mm*36+k8+tig+4];
                        af[mi][3]=As[(mm+8)*36+k8+tig+4];
                    }
                }
                #pragma unroll
                for(int ni=0;ni<4;ni++){
                    int nn=n_w+ni*8+grp;
                    bf[ni][0]=Bs[(k8+tig)*72+nn];
                    bf[ni][1]=Bs[(k8+tig+4)*72+nn];
                }
                #pragma unroll
                for(int mi=0;mi<2;mi++)
                    #pragma unroll
                    for(int ni=0;ni<4;ni++){
                        asm volatile(
                            "mma.sync.aligned.m16n8k8.row.col.f32.tf32.tf32.f32 "
                            "{%0,%1,%2,%3}, {%4,%5,%6,%7}, {%8,%9}, {%0,%1,%2,%3};"
                            : "+f"(c[mi][ni][0]), "+f"(c[mi][ni][1]),
                              "+f"(c[mi][ni][2]), "+f"(c[mi][ni][3])
                            : "r"(af[mi][0]), "r"(af[mi][1]), "r"(af[mi][2]), "r"(af[mi][3]),
                              "r"(bf[ni][0]), "r"(bf[ni][1]));
                    }
            }
            __syncthreads();
        }
    }
    #pragma unroll
    for(int mi=0;mi<2;mi++){
        int r0=m0+m_w+mi*16+grp;
        #pragma unroll
        for(int ni=0;ni<4;ni++){
            int cn=n0+n_w+ni*8+2*tig;
            float b0=0.f,b1=0.f;
            if(bias){ b0=bias[cn]; b1=bias[cn+1]; }
            float v0=c[mi][ni][0]+b0, v1=c[mi][ni][1]+b1;
            float v2=c[mi][ni][2]+b0, v3=c[mi][ni][3]+b1;
            if(relu){ v0=fmaxf(v0,0.f); v1=fmaxf(v1,0.f); v2=fmaxf(v2,0.f); v3=fmaxf(v3,0.f); }
            *(float2*)&C[(long long)r0*N+cn]      = make_float2(v0,v1);
            *(float2*)&C[(long long)(r0+8)*N+cn]  = make_float2(v2,v3);
        }
    }
}

// ---------------- small GEMM (64x64) ----------------
__global__ void k_gemm64(const float* __restrict__ A, const float* __restrict__ B,
                         const float* __restrict__ bias, float* __restrict__ C,
                         int M, int N, int K, int relu){
    __shared__ __align__(16) float As[16][65];
    __shared__ __align__(16) float Bs[16][64];
    int m0=blockIdx.y*64, n0=blockIdx.x*64;
    int t=threadIdx.x, ty=t>>4, tx=t&15;
    float acc[4][4];
    #pragma unroll
    for(int i=0;i<4;i++)
        #pragma unroll
        for(int j=0;j<4;j++) acc[i][j]=0.f;
    for(int k0=0;k0<K;k0+=16){
        {
            int r=t>>2, c=(t&3)*4;
            float4 v=*(const float4*)(A+(long long)(m0+r)*K+k0+c);
            As[c][r]=v.x; As[c+1][r]=v.y; As[c+2][r]=v.z; As[c+3][r]=v.w;
        }
        {
            int kk=t>>4, n=(t&15)*4;
            *(float4*)&Bs[kk][n]=*(const float4*)(B+(long long)(k0+kk)*N+n0+n);
        }
        __syncthreads();
        #pragma unroll
        for(int kk=0;kk<16;kk++){
            float4 b4=*(const float4*)&Bs[kk][tx*4];
            float a0=As[kk][ty*4+0], a1=As[kk][ty*4+1], a2=As[kk][ty*4+2], a3=As[kk][ty*4+3];
            acc[0][0]+=a0*b4.x; acc[0][1]+=a0*b4.y; acc[0][2]+=a0*b4.z; acc[0][3]+=a0*b4.w;
            acc[1][0]+=a1*b4.x; acc[1][1]+=a1*b4.y; acc[1][2]+=a1*b4.z; acc[1][3]+=a1*b4.w;
            acc[2][0]+=a2*b4.x; acc[2][1]+=a2*b4.y; acc[2][2]+=a2*b4.z; acc[2][3]+=a2*b4.w;
            acc[3][0]+=a3*b4.x; acc[3][1]+=a3*b4.y; acc[3][2]+=a3*b4.z; acc[3][3]+=a3*b4.w;
        }
        __syncthreads();
    }
    #pragma unroll
    for(int i=0;i<4;i++){
        int m=m0+ty*4+i;
        if(m>=M) continue;
        #pragma unroll
        for(int j=0;j<4;j++){
            int n=n0+tx*4+j;
            float v=acc[i][j];
            if(bias) v+=bias[n];
            if(relu) v=fmaxf(v,0.f);
            C[(long long)m*N+n]=v;
        }
    }
}

// ---------------- score / pnorm ----------------
__global__ void k_pnorm(const float* p, float* out){
    __shared__ float r[128]; int t=threadIdx.x;
    r[t]=p[t]*p[t]; __syncthreads();
    for(int s=64;s>0;s>>=1){ if(t<s)r[t]+=r[t+s]; __syncthreads(); }
    if(t==0) out[0]=sqrtf(r[0]);
}
__global__ void k_score(const float* __restrict__ x, const float* __restrict__ p,
                        const float* pn, float* __restrict__ out, int M){
    int w=(blockIdx.x*blockDim.x+threadIdx.x)>>5;
    int l=threadIdx.x&31;
    if(w>=M)return;
    float acc=0.f;
    #pragma unroll
    for(int q=0;q<4;q++) acc+=x[(long long)w*128+l+32*q]*p[l+32*q];
    for(int o=16;o>0;o>>=1) acc+=__shfl_down_sync(0xffffffffu,acc,o);
    if(l==0) out[w]=acc/(pn[0]+1e-16f);
}

// ---------------- per-graph bitonic top-k ----------------
__global__ void k_topk(const float* __restrict__ score, int n, int k, long long plbase){
    extern __shared__ char smraw[];
    float* ss=(float*)smraw; int* si=(int*)(ss+n);
    int b=blockIdx.x, t=threadIdx.x;
    ss[t]=score[b*n+t]; si[t]=t;
    __syncthreads();
    for(int ks=2;ks<=n;ks<<=1)
      for(int j=ks>>1;j>0;j>>=1){
        int ixj=t^j;
        if(ixj>t){
            float s1=ss[t], s2=ss[ixj]; int i1=si[t], i2=si[ixj];
            bool lt21=(s2>s1)||(s2==s1 && i2<i1);
            bool up=((t&ks)==0);
            if(up? lt21 : !lt21){ ss[t]=s2; ss[ixj]=s1; si[t]=i2; si[ixj]=i1; }
        }
        __syncthreads();
      }
    if(t<k) g_i[plbase + b*k + t] = b*n + si[t];
}
__global__ void k_mapset(long long plbase, long long prevPO, long long pobase,
                         long long cmbase, int total){
    int j=blockIdx.x*blockDim.x+threadIdx.x;
    if(j>=total)return;
    int old=g_i[plbase+j];
    int orig=(prevPO>=0)? g_i[prevPO+old] : old;
    g_i[pobase+j]=orig; g_i[cmbase+orig]=j;
}
__global__ void k_gate(const float* __restrict__ x, const float* __restrict__ score,
                       long long plbase, float* __restrict__ out){
    int j=blockIdx.x, f=threadIdx.x;
    int old=g_i[plbase+j];
    float g=tanhf(score[old]);
    out[(long long)j*128+f]=x[(long long)old*128+f]*g;
}
__global__ void k_readout(const float* __restrict__ x, int k, float* __restrict__ sxs){
    int b=blockIdx.x, f=threadIdx.x;
    float mx=-3.402823e38f, sm=0.f;
    for(int j=0;j<k;j++){
        float v=x[((long long)b*k+j)*128+f];
        mx=fmaxf(mx,v); sm+=v;
    }
    sxs[b*256+f]+=mx; sxs[b*256+128+f]+=sm/(float)k;
}

// ---------------- softmax ----------------
__global__ void k_softmax(float* __restrict__ x, int W){
    extern __shared__ float red[];
    int r=blockIdx.x, t=threadIdx.x;
    float v=x[(long long)r*W+t];
    red[t]=v; __syncthreads();
    for(int s=W>>1;s>0;s>>=1){ if(t<s)red[t]=fmaxf(red[t],red[t+s]); __syncthreads(); }
    float mx=red[0]; __syncthreads();
    float e=expf(v-mx);
    red[t]=e; __syncthreads();
    for(int s=W>>1;s>0;s>>=1){ if(t<s)red[t]+=red[t+s]; __syncthreads(); }
    x[(long long)r*W+t]=e/red[0];
}

// ---------------- mincut stats ----------------
__global__ void k_stats(const float* __restrict__ s, const float* __restrict__ oadj,
                        const float* __restrict__ ssm, const float* __restrict__ deg,
                        int n, int k, float* rout, float* oout){
    __shared__ float red[256]; __shared__ float ssn_s;
    int b=blockIdx.x, t=threadIdx.x;
    const float* sb=s+(long long)b*n*k;
    const float* ab=oadj+(long long)b*k*k;
    const float* cb=ssm+(long long)b*k*k;
    float acc=0.f;
    for(int i=t;i<k;i+=256) acc+=ab[(long long)i*(k+1)];
    red[t]=acc; __syncthreads();
    for(int st=128;st>0;st>>=1){ if(t<st)red[t]+=red[t+st]; __syncthreads(); }
    float num=red[0]; __syncthreads();
    acc=0.f;
    for(int i=t;i<n*k;i+=256){ float v=sb[i]; acc+=deg[b*n+i/k]*v*v; }
    red[t]=acc; __syncthreads();
    for(int st=128;st>0;st>>=1){ if(t<st)red[t]+=red[t+st]; __syncthreads(); }
    float den=red[0]; __syncthreads();
    acc=0.f;
    for(int i=t;i<k*k;i+=256){ float v=cb[i]; acc+=v*v; }
    red[t]=acc; __syncthreads();
    for(int st=128;st>0;st>>=1){ if(t<st)red[t]+=red[t+st]; __syncthreads(); }
    if(t==0) ssn_s=sqrtf(red[0]);
    __syncthreads();
    float ssn=ssn_s+EPSF;
    float ik=1.0f/sqrtf((float)k);
    acc=0.f;
    for(int i=t;i<k*k;i+=256){
        float v=cb[i]/ssn - (((i/k)==(i%k))? ik:0.f);
        acc+=v*v;
    }
    red[t]=acc; __syncthreads();
    for(int st=128;st>0;st>>=1){ if(t<st)red[t]+=red[t+st]; __syncthreads(); }
    if(t==0){ rout[b]=num/(den+EPSF); oout[b]=sqrtf(red[0]); }
}

// ---------------- adj post-process ----------------
__global__ void k_adjp1(float* __restrict__ adj, float* __restrict__ dp, int k){
    extern __shared__ float red[];
    int row=blockIdx.x, i=row%k, t=threadIdx.x;
    long long idx=(long long)row*k+t;
    float v=adj[idx];
    if(t==i){ v=0.f; adj[idx]=0.f; }
    red[t]=v; __syncthreads();
    for(int s=k>>1;s>0;s>>=1){ if(t<s)red[t]+=red[t+s]; __syncthreads(); }
    if(t==0) dp[row]=sqrtf(red[0])+EPSF;
}
__global__ void k_adjp2(float* __restrict__ adj, const float* __restrict__ dp,
                        float* __restrict__ rs, int k){
    extern __shared__ float red[];
    int row=blockIdx.x, b=row/k, t=threadIdx.x;
    long long idx=(long long)row*k+t;
    float v=adj[idx]/(dp[row]*dp[b*k+t]);
    adj[idx]=v;
    red[t]=v; __syncthreads();
    for(int s=k>>1;s>0;s>>=1){ if(t<s)red[t]+=red[t+s]; __syncthreads(); }
    if(t==0) rs[row]=red[0];
}
__global__ void k_nodemean(const float* __restrict__ x, float* __restrict__ out){
    int b=blockIdx.x, f=threadIdx.x;
    float sm=0.f;
    for(int j=0;j<128;j++) sm+=x[((long long)b*128+j)*128+f];
    out[b*128+f]=sm*(1.0f/128.0f);
}

// ---------------- final small layers ----------------
__global__ void k_lin2(const float* __restrict__ sxr, const float* __restrict__ xg,
                       const float* __restrict__ w, const float* __restrict__ bias,
                       float* __restrict__ out){
    int t=threadIdx.x; if(t>=640)return;
    int m=t/10, c=t%10;
    float acc=bias[c];
    for(int h=0;h<128;h++) acc+=sxr[m*128+h]*w[h*10+c];
    for(int h=0;h<128;h++) acc+=xg[m*128+h]*w[(128+h)*10+c];
    out[m*10+c]=acc;
}
__global__ void k_final(float* out, int out_size){
    __shared__ float a[64], b[64];
    int t=threadIdx.x;
    a[t]=g_f[OF_ST+t]+g_f[OF_ST+128+t];
    b[t]=g_f[OF_ST+64+t]+g_f[OF_ST+192+t];
    __syncthreads();
    for(int s=32;s>0;s>>=1){ if(t<s){a[t]+=a[t+s]; b[t]+=b[t+s];} __syncthreads(); }
    if(t==0 && out_size>=642){ out[640]=-a[0]/64.f; out[641]=b[0]/64.f; }
}

// ---------------- host side ----------------
static void gemm_f32(cudaStream_t st, const float*A, const float*B,
                     const float*bias, float*C, int M,int N,int K,int accum,int relu){
    dim3 g(N/64, M/128, 1);
    k_gemm128<false,false><<<g,256,0,st>>>(A,B,nullptr,nullptr,bias,C,M,N,K,0,0,0,accum,relu);
}
static void gemm_f32_dual(cudaStream_t st, const float*A1, const float*B1,
                          const float*A2, const float*B2,
                          const float*bias, float*C, int M,int N,int K,int relu){
    dim3 g(N/64, M/128, 1);
    k_gemm128<false,true><<<g,256,0,st>>>(A1,B1,A2,B2,bias,C,M,N,K,0,0,0,0,relu);
}
static void gemm_tc(cudaStream_t st, bool ta, const float*A, const float*B, const float*bias,
                    const float* rsA, float*C,
                    int M,int N,int K,long long sA,long long sB,long long sC,int batch,
                    int relu){
    dim3 g(N/64, M/128, batch);
    if(ta) k_gemm_tc<true ,false><<<g,256,0,st>>>(A,B,nullptr,nullptr,bias,rsA,C,M,N,K,sA,sB,sC,relu);
    else   k_gemm_tc<false,false><<<g,256,0,st>>>(A,B,nullptr,nullptr,bias,rsA,C,M,N,K,sA,sB,sC,relu);
}
static void gemm_tc_dual(const float*A1, const float*B1, const float*A2, const float*B2,
                         const float*bias, const float* rsA, float*C,
                         int M,int N,int K,int relu){
    dim3 g(N/64, M/128, 1);
    k_gemm_tc<false,true><<<g,256>>>(A1,B1,A2,B2,bias,rsA,C,M,N,K,0,0,0,relu);
}

extern "C" void kernel_launch(void* const* d_in, const int* in_sizes, int n_in,
                              void* d_out, int out_size){
    (void)in_sizes; (void)n_in;
    float* gf; int* gi;
    cudaGetSymbolAddress((void**)&gf, g_f);
    cudaGetSymbolAddress((void**)&gi, g_i);

    const float* x_in = (const float*)d_in[0];
    const int*   src  = (const int*)  d_in[1];
    const int*   dst  = (const int*)  d_in[2];
    const float* c0wr=(const float*)d_in[3], *c0wo=(const float*)d_in[4], *c0b=(const float*)d_in[5];
    const float* s2wr=(const float*)d_in[6], *s2wo=(const float*)d_in[7], *s2b=(const float*)d_in[8];
    const float* s3wr=(const float*)d_in[9], *s3wo=(const float*)d_in[10],*s3b=(const float*)d_in[11];
    const float* g1wr=(const float*)d_in[12],*g1wo=(const float*)d_in[13],*g1b=(const float*)d_in[14];
    const float* g2wr=(const float*)d_in[15],*g2wo=(const float*)d_in[16],*g2b=(const float*)d_in[17];
    const float* p0w=(const float*)d_in[18], *p0b=(const float*)d_in[19];
    const float* p1w=(const float*)d_in[20], *p1b=(const float*)d_in[21];
    const float* pv1=(const float*)d_in[22], *pv2=(const float*)d_in[23], *pv3=(const float*)d_in[24];
    const float* l11w=(const float*)d_in[25],*l11b=(const float*)d_in[26];
    const float* l1w=(const float*)d_in[27], *l1b=(const float*)d_in[28];
    const float* l2w=(const float*)d_in[29], *l2b=(const float*)d_in[30];
    float* out=(float*)d_out;

    float *X0=gf+OF_X0, *AGGB=gf+OF_AGGB, *SBIG=gf+OF_SBIG, *T1=gf+OF_T1, *XD1=gf+OF_XD1;
    float *OADJ1=gf+OF_OADJ1, *SS1=gf+OF_SS1, *XDS1=gf+OF_XDS1, *S2=gf+OF_S2, *XD2=gf+OF_XD2;
    float *T2=gf+OF_T2, *OADJ2=gf+OF_OADJ2, *SS2=gf+OF_SS2, *XDS2=gf+OF_XDS2;
    float *SXA=gf+OF_SXA, *SXB=gf+OF_SXB, *SXC=gf+OF_SXC, *SXD=gf+OF_SXD, *SXE=gf+OF_SXE;
    float *SCORE=gf+OF_SCORE, *DEG=gf+OF_DEG, *DP=gf+OF_DP, *RS1=gf+OF_RS1, *RS2=gf+OF_RS2;
    float *SXS=gf+OF_SXS, *MEAN=gf+OF_MEAN, *XG=gf+OF_XG, *SXR=gf+OF_SXR;
    float *ST=gf+OF_ST, *PN=gf+OF_PN, *SAGG=gf+OF_SAGG;
    cudaStream_t sB = g_sB, sC = g_sC;

    // ---- fork sC early: X0 = x_in @ c0wo (no CSR dependency) ----
    k_zeroi<<<256,256>>>(IO_DCNT, 65536);
    cudaEventRecord(g_ev[6], 0);
    cudaStreamWaitEvent(sC, g_ev[6], 0);
    gemm_f32(sC, x_in, c0wo, nullptr, X0, 32768,128,128, 0,0);
    k_pnorm<<<1,128,0,sC>>>(pv1,PN+0);
    k_pnorm<<<1,128,0,sC>>>(pv2,PN+1);
    k_pnorm<<<1,128,0,sC>>>(pv3,PN+2);
    cudaEventRecord(g_ev[7], sC);

    // ---- CSR build (main stream, concurrent with sC) ----
    k_zerof<<<64,256>>>(SXS, 16384);
    k_count<<<2048,256>>>(src,dst);
    { dim3 g(32,2); k_scan_blk<<<g,256>>>(); }
    k_scan_top<<<1,64>>>();
    { dim3 g(32,2); k_scan_add<<<g,256>>>(); }
    k_fill<<<2048,256>>>(src,dst);
    k_sortl<<<256,256>>>();
    k_deg1<<<128,256>>>(DEG);

    // ---- conv0: agg then accumulate onto X0 ----
    k_agg_w<<<4096,256>>>(x_in,nullptr,nullptr,src,AGGB,32768);
    cudaStreamWaitEvent(0, g_ev[7], 0);
    gemm_f32(0, AGGB, c0wr, c0b, X0, 32768,128,128, 1,1);

    // ======== fork: sparse branch on sB ========
    cudaEventRecord(g_ev[0], 0);
    cudaStreamWaitEvent(sB, g_ev[0], 0);

    k_score<<<4096,256,0,sB>>>(X0,pv1,PN+0,SCORE,32768);
    k_topk<<<64,512,512*8,sB>>>(SCORE,512,256,IO_PL1);
    k_fillneg<<<128,256,0,sB>>>(IO_CM1,32768);
    k_mapset<<<64,256,0,sB>>>(IO_PL1,-1,IO_PO1,IO_CM1,16384);
    k_gate<<<16384,128,0,sB>>>(X0,SCORE,IO_PL1,SXA);
    k_readout<<<64,128,0,sB>>>(SXA,256,SXS);
    k_agg_w<<<2048,256,0,sB>>>(SXA,gi+IO_PO1,gi+IO_CM1,src,SAGG,16384);
    gemm_f32_dual(sB, SAGG,s2wr, SXA,s2wo, s2b, SXB, 16384,128,128, 1);
    k_score<<<2048,256,0,sB>>>(SXB,pv2,PN+1,SCORE,16384);
    k_topk<<<64,256,256*8,sB>>>(SCORE,256,128,IO_PL2);
    k_fillneg<<<128,256,0,sB>>>(IO_CM2,32768);
    k_mapset<<<32,256,0,sB>>>(IO_PL2,IO_PO1,IO_PO2,IO_CM2,8192);
    k_gate<<<8192,128,0,sB>>>(SXB,SCORE,IO_PL2,SXC);
    k_readout<<<64,128,0,sB>>>(SXC,128,SXS);
    k_agg_w<<<1024,256,0,sB>>>(SXC,gi+IO_PO2,gi+IO_CM2,src,SAGG,8192);
    gemm_f32_dual(sB, SAGG,s3wr, SXC,s3wo, s3b, SXD, 8192,128,128, 1);
    k_score<<<1024,256,0,sB>>>(SXD,pv3,PN+2,SCORE,8192);
    k_topk<<<64,128,128*8,sB>>>(SCORE,128,64,IO_PL3);
    k_gate<<<4096,128,0,sB>>>(SXD,SCORE,IO_PL3,SXE);
    k_readout<<<64,128,0,sB>>>(SXE,64,SXS);
    k_gemm64<<<dim3(2,1),256,0,sB>>>(SXS,l11w,l11b,SXR, 64,128,256, 1);
    cudaEventRecord(g_ev[1], sB);

    // ---- dense branch (main + sC overlap) ----
    gemm_tc(0,false,X0,p0w,p0b,nullptr,SBIG, 32768,256,128,0,0,0,1,0);
    k_softmax<<<32768,256,256*4>>>(SBIG,256);
    cudaEventRecord(g_ev[2], 0);

    // sC: T1 = adj@SBIG, then OADJ1 = SBIG^T @ T1
    cudaStreamWaitEvent(sC, g_ev[2], 0);
    k_adjs_w<<<4096,256,0,sC>>>(SBIG,dst,T1);
    gemm_tc(sC,true,SBIG,T1,nullptr,nullptr,OADJ1, 256,256,512, 131072,131072,65536,64,0);
    cudaEventRecord(g_ev[3], sC);

    // main: XD1, SS1 in parallel with sC
    gemm_tc(0,true,SBIG,X0,nullptr,nullptr,XD1, 256,128,512, 131072,65536,32768,64,0);
    gemm_tc(0,true,SBIG,SBIG,nullptr,nullptr,SS1, 256,256,512, 131072,131072,65536,64,0);
    cudaStreamWaitEvent(0, g_ev[3], 0);

    k_stats<<<64,256>>>(SBIG,OADJ1,SS1,DEG,512,256,ST+0,ST+64);
    k_adjp1<<<16384,256,256*4>>>(OADJ1,DP,256);
    k_adjp2<<<16384,256,256*4>>>(OADJ1,DP,RS1,256);

    // sage1 (rowscale fused via rsA)
    gemm_tc(0,false,OADJ1,XD1,nullptr,nullptr,AGGB, 256,128,256, 65536,32768,32768,64,0);
    gemm_tc_dual(AGGB,g1wr, XD1,g1wo, g1b, RS1, XDS1, 16384,128,128, 1);

    // pool1 assignment + mincut 2 (T2/OADJ2 chain on sC, XD2/SS2 on main)
    gemm_tc(0,false,XDS1,p1w,p1b,nullptr,S2, 16384,128,128,0,0,0,1,0);
    k_softmax<<<16384,128,128*4>>>(S2,128);
    cudaEventRecord(g_ev[4], 0);

    cudaStreamWaitEvent(sC, g_ev[4], 0);
    gemm_tc(sC,false,OADJ1,S2,nullptr,nullptr,T2, 256,128,256, 65536,32768,32768,64,0);
    gemm_tc(sC,true,S2,T2,nullptr,nullptr,OADJ2, 128,128,256, 32768,32768,16384,64,0);
    cudaEventRecord(g_ev[5], sC);

    gemm_tc(0,true,S2,XDS1,nullptr,nullptr,XD2, 128,128,256, 32768,32768,16384,64,0);
    gemm_tc(0,true,S2,S2,nullptr,nullptr,SS2, 128,128,256, 32768,32768,16384,64,0);
    cudaStreamWaitEvent(0, g_ev[5], 0);

    k_stats<<<64,256>>>(S2,OADJ2,SS2,RS1,256,128,ST+128,ST+192);
    k_adjp1<<<8192,128,128*4>>>(OADJ2,DP,128);
    k_adjp2<<<8192,128,128*4>>>(OADJ2,DP,RS2,128);

    // sage2 (rowscale fused)
    gemm_tc(0,false,OADJ2,XD2,nullptr,nullptr,AGGB, 128,128,128, 16384,16384,16384,64,0);
    gemm_tc_dual(AGGB,g2wr, XD2,g2wo, g2b, RS2, XDS2, 8192,128,128, 0);
    k_nodemean<<<64,128>>>(XDS2,MEAN);
    k_gemm64<<<dim3(2,1),256>>>(MEAN,l1w,l1b,XG, 64,128,128, 1);

    // ======== join sparse ========
    cudaStreamWaitEvent(0, g_ev[1], 0);

    // ---- heads ----
    k_lin2<<<1,640>>>(SXR,XG,l2w,l2b,out);
    k_final<<<1,64>>>(out,out_size);
}

// round 17
// speedup vs baseline: 1.0460x; 1.0460x over previous
#include <cuda_runtime.h>
#include <cuda_fp16.h>
#include <math.h>

#define NNODE 32768
#define NEDGE 524288
#define EPSF  1e-15f

// ---------------- int scratch offsets ----------------
#define IO_DCNT  0LL
#define IO_SCNT  (IO_DCNT+32768)
#define IO_DOFF  (IO_SCNT+32768)
#define IO_SOFF  (IO_DOFF+32772)
#define IO_DCUR  (IO_SOFF+32772)
#define IO_SCUR  (IO_DCUR+32768)
#define IO_DLIST (IO_SCUR+32768)
#define IO_SLIST (IO_DLIST+524288)
#define IO_PART  (IO_SLIST+524288)
#define IO_PL1   (IO_PART+64)
#define IO_PL2   (IO_PL1+16384)
#define IO_PL3   (IO_PL2+8192)
#define IO_PO1   (IO_PL3+4096)
#define IO_PO2   (IO_PO1+16384)
#define IO_CM1   (IO_PO2+8192)
#define IO_CM2   (IO_CM1+32768)
#define I_TOT    (IO_CM2+32768)
__device__ int g_i[I_TOT];

// ---------------- float scratch offsets ----------------
#define OF_X0    0LL
#define OF_AGGB  (OF_X0+4194304)
#define OF_SBIG  (OF_AGGB+4194304)
#define OF_T1    (OF_SBIG+8388608)
#define OF_XD1   (OF_T1+8388608)
#define OF_OADJ1 (OF_XD1+2097152)
#define OF_SS1   (OF_OADJ1+4194304)
#define OF_XDS1  (OF_SS1+4194304)
#define OF_S2    (OF_XDS1+2097152)
#define OF_XD2   (OF_S2+2097152)
#define OF_T2    (OF_XD2+1048576)
#define OF_OADJ2 (OF_T2+2097152)
#define OF_SS2   (OF_OADJ2+1048576)
#define OF_XDS2  (OF_SS2+1048576)
#define OF_SXA   (OF_XDS2+1048576)
#define OF_SXB   (OF_SXA+2097152)
#define OF_SXC   (OF_SXB+2097152)
#define OF_SXD   (OF_SXC+1048576)
#define OF_SXE   (OF_SXD+1048576)
#define OF_SCORE (OF_SXE+524288)
#define OF_DEG   (OF_SCORE+32768)
#define OF_DP    (OF_DEG+32768)
#define OF_RS1   (OF_DP+16384)
#define OF_RS2   (OF_RS1+16384)
#define OF_SXS   (OF_RS2+8192)
#define OF_MEAN  (OF_SXS+16384)
#define OF_XG    (OF_MEAN+8192)
#define OF_SXR   (OF_XG+8192)
#define OF_ST    (OF_SXR+8192)
#define OF_PN    (OF_ST+256)
#define OF_SAGG  (OF_PN+16)
#define F_TOT    (OF_SAGG+2097152)
__device__ float g_f[F_TOT];

// ---------------- streams/events (static init) ----------------
static cudaStream_t g_sB = 0, g_sC = 0;
static cudaEvent_t  g_ev[8];
struct _StreamInit {
    _StreamInit(){
        cudaStreamCreateWithFlags(&g_sB, cudaStreamNonBlocking);
        cudaStreamCreateWithFlags(&g_sC, cudaStreamNonBlocking);
        for(int i=0;i<8;i++) cudaEventCreateWithFlags(&g_ev[i], cudaEventDisableTiming);
    }
};
static _StreamInit g_stream_init;

// ---------------- utility ----------------
__global__ void k_zerof(float* p, long long n){
    long long i=(long long)blockIdx.x*blockDim.x+threadIdx.x; if(i<n)p[i]=0.f;
}
__global__ void k_zeroi(long long base, long long n){
    long long i=(long long)blockIdx.x*blockDim.x+threadIdx.x; if(i<n)g_i[base+i]=0;
}
__global__ void k_fillneg(long long base, long long n){
    long long i=(long long)blockIdx.x*blockDim.x+threadIdx.x; if(i<n)g_i[base+i]=-1;
}

// ---------------- CSR build ----------------
__global__ void k_count(const int* __restrict__ src, const int* __restrict__ dst){
    int e=blockIdx.x*blockDim.x+threadIdx.x;
    if(e<NEDGE){ atomicAdd(&g_i[IO_DCNT+dst[e]],1); atomicAdd(&g_i[IO_SCNT+src[e]],1); }
}
__global__ void k_scan_blk(){
    int pass=blockIdx.y;
    long long cb = pass? IO_SCNT:IO_DCNT;
    long long ob = pass? IO_SOFF:IO_DOFF;
    int base = blockIdx.x*1024 + threadIdx.x*4;
    int4 v = *(const int4*)&g_i[cb+base];
    int s = v.x+v.y+v.z+v.w;
    int lane=threadIdx.x&31, wid=threadIdx.x>>5;
    int p=s;
    #pragma unroll
    for(int o=1;o<32;o<<=1){ int u=__shfl_up_sync(0xffffffffu,p,o); if(lane>=o)p+=u; }
    __shared__ int ws[8];
    if(lane==31) ws[wid]=p;
    __syncthreads();
    if(threadIdx.x<8){
        int u=ws[threadIdx.x];
        #pragma unroll
        for(int o=1;o<8;o<<=1){ int q=__shfl_up_sync(0xffu,u,o); if((int)threadIdx.x>=o)u+=q; }
        ws[threadIdx.x]=u;
    }
    __syncthreads();
    int excl = p - s + (wid? ws[wid-1]:0);
    int4 w4; w4.x=excl; w4.y=w4.x+v.x; w4.z=w4.y+v.y; w4.w=w4.z+v.z;
    *(int4*)&g_i[ob+base]=w4;
    if(threadIdx.x==255) g_i[IO_PART + pass*32 + blockIdx.x] = excl + s;
}
__global__ void k_scan_top(){
    int t=threadIdx.x; if(t>=64)return;
    int lane=t&31;
    int v=g_i[IO_PART+t];
    int p=v;
    #pragma unroll
    for(int o=1;o<32;o<<=1){ int u=__shfl_up_sync(0xffffffffu,p,o); if(lane>=o)p+=u; }
    g_i[IO_PART+t]=p-v;
}
__global__ void k_scan_add(){
    int pass=blockIdx.y;
    long long ob = pass? IO_SOFF:IO_DOFF;
    long long ub = pass? IO_SCUR:IO_DCUR;
    int add = g_i[IO_PART+pass*32+blockIdx.x];
    int base = blockIdx.x*1024 + threadIdx.x*4;
    int4 v=*(const int4*)&g_i[ob+base];
    v.x+=add; v.y+=add; v.z+=add; v.w+=add;
    *(int4*)&g_i[ob+base]=v;
    *(int4*)&g_i[ub+base]=v;
    if(blockIdx.x==0&&threadIdx.x==0) g_i[ob+NNODE]=NEDGE;
}
__global__ void k_fill(const int* __restrict__ src, const int* __restrict__ dst){
    int e=blockIdx.x*blockDim.x+threadIdx.x;
    if(e<NEDGE){
        int p=atomicAdd(&g_i[IO_DCUR+dst[e]],1); g_i[IO_DLIST+p]=e;
        int q=atomicAdd(&g_i[IO_SCUR+src[e]],1); g_i[IO_SLIST+q]=e;
    }
}
__global__ void k_sortl(){
    int v=blockIdx.x*blockDim.x+threadIdx.x;
    if(v>=2*NNODE)return;
    int which=v/NNODE, node=v%NNODE;
    long long ob=which?IO_SOFF:IO_DOFF, lb=which?IO_SLIST:IO_DLIST;
    int a=g_i[ob+node], b=g_i[ob+node+1];
    for(int i=a+1;i<b;i++){
        int key=g_i[lb+i]; int j=i-1;
        while(j>=a && g_i[lb+j]>key){ g_i[lb+j+1]=g_i[lb+j]; j--; }
        g_i[lb+j+1]=key;
    }
}
__global__ void k_deg1(float* deg){
    int v=blockIdx.x*blockDim.x+threadIdx.x;
    if(v<NNODE) deg[v]=(float)(g_i[IO_SOFF+v+1]-g_i[IO_SOFF+v]);
}

// ---------------- graph-conv aggregation (warp per node, float4) ----------------
__global__ void k_agg_w(const float* __restrict__ x, const int* __restrict__ permO,
                        const int* __restrict__ cmap, const int* __restrict__ src,
                        float* __restrict__ out, int nn){
    int gw=(blockIdx.x*blockDim.x+threadIdx.x)>>5;
    int lane=threadIdx.x&31;
    if(gw>=nn)return;
    int v=permO?permO[gw]:gw;
    int s0=g_i[IO_DOFF+v], s1=g_i[IO_DOFF+v+1];
    float4 acc=make_float4(0.f,0.f,0.f,0.f);
    for(int p=s0;p<s1;p++){
        int e=g_i[IO_DLIST+p];
        int sv=src[e];
        int r=cmap?cmap[sv]:sv;
        if(r>=0){
            float4 u=*(const float4*)&x[(long long)r*128+lane*4];
            acc.x+=u.x; acc.y+=u.y; acc.z+=u.z; acc.w+=u.w;
        }
    }
    *(float4*)&out[(long long)gw*128+lane*4]=acc;
}
__global__ void k_adjs_w(const float* __restrict__ s, const int* __restrict__ dst,
                         float* __restrict__ T){
    int gw=(blockIdx.x*blockDim.x+threadIdx.x)>>5;
    int lane=threadIdx.x&31;
    if(gw>=NNODE)return;
    int s0=g_i[IO_SOFF+gw], s1=g_i[IO_SOFF+gw+1];
    float4 a0=make_float4(0.f,0.f,0.f,0.f), a1=a0;
    for(int p=s0;p<s1;p++){
        int e=g_i[IO_SLIST+p];
        const float4* row=(const float4*)&s[(long long)dst[e]*256];
        float4 u0=row[lane], u1=row[lane+32];
        a0.x+=u0.x; a0.y+=u0.y; a0.z+=u0.z; a0.w+=u0.w;
        a1.x+=u1.x; a1.y+=u1.y; a1.z+=u1.z; a1.w+=u1.w;
    }
    float4* o=(float4*)&T[(long long)gw*256];
    o[lane]=a0; o[lane+32]=a1;
}

// ---------------- fp32 tiled GEMM (sparse branch + conv0) ----------------
template<bool TA, bool DUAL>
__global__ void k_gemm128(const float* __restrict__ A, const float* __restrict__ B,
                          const float* __restrict__ A2, const float* __restrict__ B2,
                          const float* __restrict__ bias, float* __restrict__ C,
                          int M, int N, int K,
                          long long sA, long long sB, long long sC,
                          int accum, int relu){
    __shared__ __align__(16) float As[16][132];
    __shared__ __align__(16) float Bs[16][68];
    A += (long long)blockIdx.z*sA; B += (long long)blockIdx.z*sB; C += (long long)blockIdx.z*sC;
    if(DUAL){ A2 += (long long)blockIdx.z*sA; B2 += (long long)blockIdx.z*sB; }
    int m0=blockIdx.y*128, n0=blockIdx.x*64;
    int t=threadIdx.x, ty=t>>4, tx=t&15;
    float acc[8][4];
    #pragma unroll
    for(int i=0;i<8;i++)
        #pragma unroll
        for(int j=0;j<4;j++) acc[i][j]=0.f;
    #pragma unroll 1
    for(int pass=0; pass<(DUAL?2:1); pass++){
        const float* Ap = pass? A2 : A;
        const float* Bp = pass? B2 : B;
        for(int k0=0;k0<K;k0+=16){
            if(TA){
                int kk=t>>4, m=(t&15)*8;
                const float* p = Ap + (long long)(k0+kk)*M + m0 + m;
                float4 v0=*(const float4*)p, v1=*(const float4*)(p+4);
                As[kk][m+0]=v0.x; As[kk][m+1]=v0.y; As[kk][m+2]=v0.z; As[kk][m+3]=v0.w;
                As[kk][m+4]=v1.x; As[kk][m+5]=v1.y; As[kk][m+6]=v1.z; As[kk][m+7]=v1.w;
            }else{
                int r=t>>1, c=(t&1)*8;
                const float* p = Ap + (long long)(m0+r)*K + k0 + c;
                float4 v0=*(const float4*)p, v1=*(const float4*)(p+4);
                As[c+0][r]=v0.x; As[c+1][r]=v0.y; As[c+2][r]=v0.z; As[c+3][r]=v0.w;
                As[c+4][r]=v1.x; As[c+5][r]=v1.y; As[c+6][r]=v1.z; As[c+7][r]=v1.w;
            }
            {
                int kk=t>>4, n=(t&15)*4;
                *(float4*)&Bs[kk][n]=*(const float4*)(Bp + (long long)(k0+kk)*N + n0 + n);
            }
            __syncthreads();
            #pragma unroll
            for(int kk=0;kk<16;kk++){
                float4 b4=*(const float4*)&Bs[kk][tx*4];
                float4 a0=*(const float4*)&As[kk][ty*8];
                float4 a1=*(const float4*)&As[kk][ty*8+4];
                acc[0][0]+=a0.x*b4.x; acc[0][1]+=a0.x*b4.y; acc[0][2]+=a0.x*b4.z; acc[0][3]+=a0.x*b4.w;
                acc[1][0]+=a0.y*b4.x; acc[1][1]+=a0.y*b4.y; acc[1][2]+=a0.y*b4.z; acc[1][3]+=a0.y*b4.w;
                acc[2][0]+=a0.z*b4.x; acc[2][1]+=a0.z*b4.y; acc[2][2]+=a0.z*b4.z; acc[2][3]+=a0.z*b4.w;
                acc[3][0]+=a0.w*b4.x; acc[3][1]+=a0.w*b4.y; acc[3][2]+=a0.w*b4.z; acc[3][3]+=a0.w*b4.w;
                acc[4][0]+=a1.x*b4.x; acc[4][1]+=a1.x*b4.y; acc[4][2]+=a1.x*b4.z; acc[4][3]+=a1.x*b4.w;
                acc[5][0]+=a1.y*b4.x; acc[5][1]+=a1.y*b4.y; acc[5][2]+=a1.y*b4.z; acc[5][3]+=a1.y*b4.w;
                acc[6][0]+=a1.z*b4.x; acc[6][1]+=a1.z*b4.y; acc[6][2]+=a1.z*b4.z; acc[6][3]+=a1.z*b4.w;
                acc[7][0]+=a1.w*b4.x; acc[7][1]+=a1.w*b4.y; acc[7][2]+=a1.w*b4.z; acc[7][3]+=a1.w*b4.w;
            }
            __syncthreads();
        }
    }
    float4 bb=make_float4(0.f,0.f,0.f,0.f);
    if(bias) bb=*(const float4*)(bias+n0+tx*4);
    #pragma unroll
    for(int i=0;i<8;i++){
        long long m=m0+ty*8+i;
        float4 v=make_float4(acc[i][0],acc[i][1],acc[i][2],acc[i][3]);
        float4* cp=(float4*)&C[m*N + n0 + tx*4];
        if(accum){ float4 o=*cp; v.x+=o.x; v.y+=o.y; v.z+=o.z; v.w+=o.w; }
        v.x+=bb.x; v.y+=bb.y; v.z+=bb.z; v.w+=bb.w;
        if(relu){ v.x=fmaxf(v.x,0.f); v.y=fmaxf(v.y,0.f); v.z=fmaxf(v.z,0.f); v.w=fmaxf(v.w,0.f); }
        *cp=v;
    }
}

// ---------------- fp16 tensor-core GEMM (m16n8k16, fp32 accumulate) ----------------
// fp16 mantissa == tf32 mantissa -> precision-neutral vs tf32; 2x K per MMA.
__device__ __forceinline__ unsigned packh(float a, float b){
    __half2 h=__floats2half2_rn(a,b);
    return *(unsigned*)&h;
}
template<bool TA, bool DUAL>
__global__ void k_gemm_tc(const float* __restrict__ A, const float* __restrict__ B,
                          const float* __restrict__ A2, const float* __restrict__ B2,
                          const float* __restrict__ bias, const float* __restrict__ rsA,
                          float* __restrict__ C,
                          int M, int N, int K,
                          long long sA, long long sB, long long sC, int relu){
    // non-TA: Am[m][kpair], stride 20 (16+4 pad), 128 rows  -> 2560 u
    // TA:     Ak[kpair][m], stride 132 (128+4), 16 rows      -> 2112 u
    // B:      Bh[kpair][n], stride 72 (64+8),  16 rows       -> 1152 u
    __shared__ __align__(16) unsigned Ah[2560];
    __shared__ __align__(16) unsigned Bh[1152];
    A += (long long)blockIdx.z*sA; B += (long long)blockIdx.z*sB; C += (long long)blockIdx.z*sC;
    if(DUAL){ A2 += (long long)blockIdx.z*sA; B2 += (long long)blockIdx.z*sB; }
    int m0=blockIdx.y*128, n0=blockIdx.x*64;
    int t=threadIdx.x, w=t>>5, lane=t&31;
    int grp=lane>>2, tig=lane&3;
    int m_w=(w&3)*32, n_w=(w>>2)*32;
    float c[2][4][4];
    #pragma unroll
    for(int a=0;a<2;a++)
        #pragma unroll
        for(int b=0;b<4;b++)
            #pragma unroll
            for(int q=0;q<4;q++) c[a][b][q]=0.f;
    #pragma unroll 1
    for(int pass=0; pass<(DUAL?2:1); pass++){
        const float* Ap = pass? A2 : A;
        const float* Bp = pass? B2 : B;
        #pragma unroll 1
        for(int k0=0;k0<K;k0+=32){
            // ---- A tile ----
            if(TA){
                // chunk 32k x 128m; thread: kpair j=t>>4, 8 m's at mb
                int j=t>>4, mb=(t&15)*8;
                const float* r0=Ap + (long long)(k0+2*j)*M + m0 + mb;
                const float* r1=Ap + (long long)(k0+2*j+1)*M + m0 + mb;
                float4 a0=*(const float4*)r0, a1=*(const float4*)(r0+4);
                float4 b0=*(const float4*)r1, b1=*(const float4*)(r1+4);
                uint4 u0, u1;
                u0.x=packh(a0.x,b0.x); u0.y=packh(a0.y,b0.y);
                u0.z=packh(a0.z,b0.z); u0.w=packh(a0.w,b0.w);
                u1.x=packh(a1.x,b1.x); u1.y=packh(a1.y,b1.y);
                u1.z=packh(a1.z,b1.z); u1.w=packh(a1.w,b1.w);
                *(uint4*)&Ah[j*132+mb]   = u0;
                *(uint4*)&Ah[j*132+mb+4] = u1;
            }else{
                // chunk 128m x 32k; 4 passes, thread: m=idx>>5, kb=idx&31
                #pragma unroll
                for(int p=0;p<4;p++){
                    int idx=p*1024+t*4;
                    int m=idx>>5, kb=idx&31;
                    float4 v=*(const float4*)(Ap + (long long)(m0+m)*K + k0 + kb);
                    if(rsA && pass==0){
                        float sc=1.f/fmaxf(rsA[m0+m],1.f);
                        v.x*=sc; v.y*=sc; v.z*=sc; v.w*=sc;
                    }
                    uint2 u; u.x=packh(v.x,v.y); u.y=packh(v.z,v.w);
                    *(uint2*)&Ah[m*20+(kb>>1)] = u;
                }
            }
            // ---- B tile: chunk 32k x 64n; thread: kpair j=t>>4, 4 n's ----
            {
                int j=t>>4, nb=(t&15)*4;
                float4 b0=*(const float4*)(Bp + (long long)(k0+2*j)*N + n0 + nb);
                float4 b1=*(const float4*)(Bp + (long long)(k0+2*j+1)*N + n0 + nb);
                uint4 u;
                u.x=packh(b0.x,b1.x); u.y=packh(b0.y,b1.y);
                u.z=packh(b0.z,b1.z); u.w=packh(b0.w,b1.w);
                *(uint4*)&Bh[j*72+nb] = u;
            }
            __syncthreads();
            #pragma unroll
            for(int kg=0;kg<2;kg++){
                int j0=kg*8;
                unsigned af[2][4], bf[4][2];
                #pragma unroll
                for(int mi=0;mi<2;mi++){
                    int mm=m_w+mi*16+grp;
                    if(TA){
                        af[mi][0]=Ah[(j0+tig)*132+mm];
                        af[mi][1]=Ah[(j0+tig)*132+mm+8];
                        af[mi][2]=Ah[(j0+4+tig)*132+mm];
                        af[mi][3]=Ah[(j0+4+tig)*132+mm+8];
                    }else{
                        af[mi][0]=Ah[mm*20+j0+tig];
                        af[mi][1]=Ah[(mm+8)*20+j0+tig];
                        af[mi][2]=Ah[mm*20+j0+4+tig];
                        af[mi][3]=Ah[(mm+8)*20+j0+4+tig];
                    }
                }
                #pragma unroll
                for(int ni=0;ni<4;ni++){
                    int nn=n_w+ni*8+grp;
                    bf[ni][0]=Bh[(j0+tig)*72+nn];
                    bf[ni][1]=Bh[(j0+4+tig)*72+nn];
                }
                #pragma unroll
                for(int mi=0;mi<2;mi++)
                    #pragma unroll
                    for(int ni=0;ni<4;ni++){
                        asm volatile(
                            "mma.sync.aligned.m16n8k16.row.col.f32.f16.f16.f32 "
                            "{%0,%1,%2,%3}, {%4,%5,%6,%7}, {%8,%9}, {%0,%1,%2,%3};"
                            : "+f"(c[mi][ni][0]), "+f"(c[mi][ni][1]),
                              "+f"(c[mi][ni][2]), "+f"(c[mi][ni][3])
                            : "r"(af[mi][0]), "r"(af[mi][1]), "r"(af[mi][2]), "r"(af[mi][3]),
                              "r"(bf[ni][0]), "r"(bf[ni][1]));
                    }
            }
            __syncthreads();
        }
    }
    #pragma unroll
    for(int mi=0;mi<2;mi++){
        int r0=m0+m_w+mi*16+grp;
        #pragma unroll
        for(int ni=0;ni<4;ni++){
            int cn=n0+n_w+ni*8+2*tig;
            float b0=0.f,b1=0.f;
            if(bias){ b0=bias[cn]; b1=bias[cn+1]; }
            float v0=c[mi][ni][0]+b0, v1=c[mi][ni][1]+b1;
            float v2=c[mi][ni][2]+b0, v3=c[mi][ni][3]+b1;
            if(relu){ v0=fmaxf(v0,0.f); v1=fmaxf(v1,0.f); v2=fmaxf(v2,0.f); v3=fmaxf(v3,0.f); }
            *(float2*)&C[(long long)r0*N+cn]      = make_float2(v0,v1);
            *(float2*)&C[(long long)(r0+8)*N+cn]  = make_float2(v2,v3);
        }
    }
}

// ---------------- small GEMM (64x64) ----------------
__global__ void k_gemm64(const float* __restrict__ A, const float* __restrict__ B,
                         const float* __restrict__ bias, float* __restrict__ C,
                         int M, int N, int K, int relu){
    __shared__ __align__(16) float As[16][65];
    __shared__ __align__(16) float Bs[16][64];
    int m0=blockIdx.y*64, n0=blockIdx.x*64;
    int t=threadIdx.x, ty=t>>4, tx=t&15;
    float acc[4][4];
    #pragma unroll
    for(int i=0;i<4;i++)
        #pragma unroll
        for(int j=0;j<4;j++) acc[i][j]=0.f;
    for(int k0=0;k0<K;k0+=16){
        {
            int r=t>>2, c=(t&3)*4;
            float4 v=*(const float4*)(A+(long long)(m0+r)*K+k0+c);
            As[c][r]=v.x; As[c+1][r]=v.y; As[c+2][r]=v.z; As[c+3][r]=v.w;
        }
        {
            int kk=t>>4, n=(t&15)*4;
            *(float4*)&Bs[kk][n]=*(const float4*)(B+(long long)(k0+kk)*N+n0+n);
        }
        __syncthreads();
        #pragma unroll
        for(int kk=0;kk<16;kk++){
            float4 b4=*(const float4*)&Bs[kk][tx*4];
            float a0=As[kk][ty*4+0], a1=As[kk][ty*4+1], a2=As[kk][ty*4+2], a3=As[kk][ty*4+3];
            acc[0][0]+=a0*b4.x; acc[0][1]+=a0*b4.y; acc[0][2]+=a0*b4.z; acc[0][3]+=a0*b4.w;
            acc[1][0]+=a1*b4.x; acc[1][1]+=a1*b4.y; acc[1][2]+=a1*b4.z; acc[1][3]+=a1*b4.w;
            acc[2][0]+=a2*b4.x; acc[2][1]+=a2*b4.y; acc[2][2]+=a2*b4.z; acc[2][3]+=a2*b4.w;
            acc[3][0]+=a3*b4.x; acc[3][1]+=a3*b4.y; acc[3][2]+=a3*b4.z; acc[3][3]+=a3*b4.w;
        }
        __syncthreads();
    }
    #pragma unroll
    for(int i=0;i<4;i++){
        int m=m0+ty*4+i;
        if(m>=M) continue;
        #pragma unroll
        for(int j=0;j<4;j++){
            int n=n0+tx*4+j;
            float v=acc[i][j];
            if(bias) v+=bias[n];
            if(relu) v=fmaxf(v,0.f);
            C[(long long)m*N+n]=v;
        }
    }
}

// ---------------- score / pnorm ----------------
__global__ void k_pnorm(const float* p, float* out){
    __shared__ float r[128]; int t=threadIdx.x;
    r[t]=p[t]*p[t]; __syncthreads();
    for(int s=64;s>0;s>>=1){ if(t<s)r[t]+=r[t+s]; __syncthreads(); }
    if(t==0) out[0]=sqrtf(r[0]);
}
__global__ void k_score(const float* __restrict__ x, const float* __restrict__ p,
                        const float* pn, float* __restrict__ out, int M){
    int w=(blockIdx.x*blockDim.x+threadIdx.x)>>5;
    int l=threadIdx.x&31;
    if(w>=M)return;
    float acc=0.f;
    #pragma unroll
    for(int q=0;q<4;q++) acc+=x[(long long)w*128+l+32*q]*p[l+32*q];
    for(int o=16;o>0;o>>=1) acc+=__shfl_down_sync(0xffffffffu,acc,o);
    if(l==0) out[w]=acc/(pn[0]+1e-16f);
}

// ---------------- per-graph bitonic top-k ----------------
__global__ void k_topk(const float* __restrict__ score, int n, int k, long long plbase){
    extern __shared__ char smraw[];
    float* ss=(float*)smraw; int* si=(int*)(ss+n);
    int b=blockIdx.x, t=threadIdx.x;
    ss[t]=score[b*n+t]; si[t]=t;
    __syncthreads();
    for(int ks=2;ks<=n;ks<<=1)
      for(int j=ks>>1;j>0;j>>=1){
        int ixj=t^j;
        if(ixj>t){
            float s1=ss[t], s2=ss[ixj]; int i1=si[t], i2=si[ixj];
            bool lt21=(s2>s1)||(s2==s1 && i2<i1);
            bool up=((t&ks)==0);
            if(up? lt21 : !lt21){ ss[t]=s2; ss[ixj]=s1; si[t]=i2; si[ixj]=i1; }
        }
        __syncthreads();
      }
    if(t<k) g_i[plbase + b*k + t] = b*n + si[t];
}
__global__ void k_mapset(long long plbase, long long prevPO, long long pobase,
                         long long cmbase, int total){
    int j=blockIdx.x*blockDim.x+threadIdx.x;
    if(j>=total)return;
    int old=g_i[plbase+j];
    int orig=(prevPO>=0)? g_i[prevPO+old] : old;
    g_i[pobase+j]=orig; g_i[cmbase+orig]=j;
}
__global__ void k_gate(const float* __restrict__ x, const float* __restrict__ score,
                       long long plbase, float* __restrict__ out){
    int j=blockIdx.x, f=threadIdx.x;
    int old=g_i[plbase+j];
    float g=tanhf(score[old]);
    out[(long long)j*128+f]=x[(long long)old*128+f]*g;
}
__global__ void k_readout(const float* __restrict__ x, int k, float* __restrict__ sxs){
    int b=blockIdx.x, f=threadIdx.x;
    float mx=-3.402823e38f, sm=0.f;
    for(int j=0;j<k;j++){
        float v=x[((long long)b*k+j)*128+f];
        mx=fmaxf(mx,v); sm+=v;
    }
    sxs[b*256+f]+=mx; sxs[b*256+128+f]+=sm/(float)k;
}

// ---------------- softmax ----------------
__global__ void k_softmax(float* __restrict__ x, int W){
    extern __shared__ float red[];
    int r=blockIdx.x, t=threadIdx.x;
    float v=x[(long long)r*W+t];
    red[t]=v; __syncthreads();
    for(int s=W>>1;s>0;s>>=1){ if(t<s)red[t]=fmaxf(red[t],red[t+s]); __syncthreads(); }
    float mx=red[0]; __syncthreads();
    float e=expf(v-mx);
    red[t]=e; __syncthreads();
    for(int s=W>>1;s>0;s>>=1){ if(t<s)red[t]+=red[t+s]; __syncthreads(); }
    x[(long long)r*W+t]=e/red[0];
}

// ---------------- mincut stats ----------------
__global__ void k_stats(const float* __restrict__ s, const float* __restrict__ oadj,
                        const float* __restrict__ ssm, const float* __restrict__ deg,
                        int n, int k, float* rout, float* oout){
    __shared__ float red[256]; __shared__ float ssn_s;
    int b=blockIdx.x, t=threadIdx.x;
    const float* sb=s+(long long)b*n*k;
    const float* ab=oadj+(long long)b*k*k;
    const float* cb=ssm+(long long)b*k*k;
    float acc=0.f;
    for(int i=t;i<k;i+=256) acc+=ab[(long long)i*(k+1)];
    red[t]=acc; __syncthreads();
    for(int st=128;st>0;st>>=1){ if(t<st)red[t]+=red[t+st]; __syncthreads(); }
    float num=red[0]; __syncthreads();
    acc=0.f;
    for(int i=t;i<n*k;i+=256){ float v=sb[i]; acc+=deg[b*n+i/k]*v*v; }
    red[t]=acc; __syncthreads();
    for(int st=128;st>0;st>>=1){ if(t<st)red[t]+=red[t+st]; __syncthreads(); }
    float den=red[0]; __syncthreads();
    acc=0.f;
    for(int i=t;i<k*k;i+=256){ float v=cb[i]; acc+=v*v; }
    red[t]=acc; __syncthreads();
    for(int st=128;st>0;st>>=1){ if(t<st)red[t]+=red[t+st]; __syncthreads(); }
    if(t==0) ssn_s=sqrtf(red[0]);
    __syncthreads();
    float ssn=ssn_s+EPSF;
    float ik=1.0f/sqrtf((float)k);
    acc=0.f;
    for(int i=t;i<k*k;i+=256){
        float v=cb[i]/ssn - (((i/k)==(i%k))? ik:0.f);
        acc+=v*v;
    }
    red[t]=acc; __syncthreads();
    for(int st=128;st>0;st>>=1){ if(t<st)red[t]+=red[t+st]; __syncthreads(); }
    if(t==0){ rout[b]=num/(den+EPSF); oout[b]=sqrtf(red[0]); }
}

// ---------------- adj post-process ----------------
__global__ void k_adjp1(float* __restrict__ adj, float* __restrict__ dp, int k){
    extern __shared__ float red[];
    int row=blockIdx.x, i=row%k, t=threadIdx.x;
    long long idx=(long long)row*k+t;
    float v=adj[idx];
    if(t==i){ v=0.f; adj[idx]=0.f; }
    red[t]=v; __syncthreads();
    for(int s=k>>1;s>0;s>>=1){ if(t<s)red[t]+=red[t+s]; __syncthreads(); }
    if(t==0) dp[row]=sqrtf(red[0])+EPSF;
}
__global__ void k_adjp2(float* __restrict__ adj, const float* __restrict__ dp,
                        float* __restrict__ rs, int k){
    extern __shared__ float red[];
    int row=blockIdx.x, b=row/k, t=threadIdx.x;
    long long idx=(long long)row*k+t;
    float v=adj[idx]/(dp[row]*dp[b*k+t]);
    adj[idx]=v;
    red[t]=v; __syncthreads();
    for(int s=k>>1;s>0;s>>=1){ if(t<s)red[t]+=red[t+s]; __syncthreads(); }
    if(t==0) rs[row]=red[0];
}
__global__ void k_nodemean(const float* __restrict__ x, float* __restrict__ out){
    int b=blockIdx.x, f=threadIdx.x;
    float sm=0.f;
    for(int j=0;j<128;j++) sm+=x[((long long)b*128+j)*128+f];
    out[b*128+f]=sm*(1.0f/128.0f);
}

// ---------------- final small layers ----------------
__global__ void k_lin2(const float* __restrict__ sxr, const float* __restrict__ xg,
                       const float* __restrict__ w, const float* __restrict__ bias,
                       float* __restrict__ out){
    int t=threadIdx.x; if(t>=640)return;
    int m=t/10, c=t%10;
    float acc=bias[c];
    for(int h=0;h<128;h++) acc+=sxr[m*128+h]*w[h*10+c];
    for(int h=0;h<128;h++) acc+=xg[m*128+h]*w[(128+h)*10+c];
    out[m*10+c]=acc;
}
__global__ void k_final(float* out, int out_size){
    __shared__ float a[64], b[64];
    int t=threadIdx.x;
    a[t]=g_f[OF_ST+t]+g_f[OF_ST+128+t];
    b[t]=g_f[OF_ST+64+t]+g_f[OF_ST+192+t];
    __syncthreads();
    for(int s=32;s>0;s>>=1){ if(t<s){a[t]+=a[t+s]; b[t]+=b[t+s];} __syncthreads(); }
    if(t==0 && out_size>=642){ out[640]=-a[0]/64.f; out[641]=b[0]/64.f; }
}

// ---------------- host side ----------------
static void gemm_f32_dual(cudaStream_t st, const float*A1, const float*B1,
                          const float*A2, const float*B2,
                          const float*bias, float*C, int M,int N,int K,int relu){
    dim3 g(N/64, M/128, 1);
    k_gemm128<false,true><<<g,256,0,st>>>(A1,B1,A2,B2,bias,C,M,N,K,0,0,0,0,relu);
}
static void gemm_tc(cudaStream_t st, bool ta, const float*A, const float*B, const float*bias,
                    const float* rsA, float*C,
                    int M,int N,int K,long long sA,long long sB,long long sC,int batch,
                    int relu){
    dim3 g(N/64, M/128, batch);
    if(ta) k_gemm_tc<true ,false><<<g,256,0,st>>>(A,B,nullptr,nullptr,bias,rsA,C,M,N,K,sA,sB,sC,relu);
    else   k_gemm_tc<false,false><<<g,256,0,st>>>(A,B,nullptr,nullptr,bias,rsA,C,M,N,K,sA,sB,sC,relu);
}
static void gemm_tc_dual(const float*A1, const float*B1, const float*A2, const float*B2,
                         const float*bias, const float* rsA, float*C,
                         int M,int N,int K,int relu){
    dim3 g(N/64, M/128, 1);
    k_gemm_tc<false,true><<<g,256>>>(A1,B1,A2,B2,bias,rsA,C,M,N,K,0,0,0,relu);
}

extern "C" void kernel_launch(void* const* d_in, const int* in_sizes, int n_in,
                              void* d_out, int out_size){
    (void)in_sizes; (void)n_in;
    float* gf; int* gi;
    cudaGetSymbolAddress((void**)&gf, g_f);
    cudaGetSymbolAddress((void**)&gi, g_i);

    const float* x_in = (const float*)d_in[0];
    const int*   src  = (const int*)  d_in[1];
    const int*   dst  = (const int*)  d_in[2];
    const float* c0wr=(const float*)d_in[3], *c0wo=(const float*)d_in[4], *c0b=(const float*)d_in[5];
    const float* s2wr=(const float*)d_in[6], *s2wo=(const float*)d_in[7], *s2b=(const float*)d_in[8];
    const float* s3wr=(const float*)d_in[9], *s3wo=(const float*)d_in[10],*s3b=(const float*)d_in[11];
    const float* g1wr=(const float*)d_in[12],*g1wo=(const float*)d_in[13],*g1b=(const float*)d_in[14];
    const float* g2wr=(const float*)d_in[15],*g2wo=(const float*)d_in[16],*g2b=(const float*)d_in[17];
    const float* p0w=(const float*)d_in[18], *p0b=(const float*)d_in[19];
    const float* p1w=(const float*)d_in[20], *p1b=(const float*)d_in[21];
    const float* pv1=(const float*)d_in[22], *pv2=(const float*)d_in[23], *pv3=(const float*)d_in[24];
    const float* l11w=(const float*)d_in[25],*l11b=(const float*)d_in[26];
    const float* l1w=(const float*)d_in[27], *l1b=(const float*)d_in[28];
    const float* l2w=(const float*)d_in[29], *l2b=(const float*)d_in[30];
    float* out=(float*)d_out;

    float *X0=gf+OF_X0, *AGGB=gf+OF_AGGB, *SBIG=gf+OF_SBIG, *T1=gf+OF_T1, *XD1=gf+OF_XD1;
    float *OADJ1=gf+OF_OADJ1, *SS1=gf+OF_SS1, *XDS1=gf+OF_XDS1, *S2=gf+OF_S2, *XD2=gf+OF_XD2;
    float *T2=gf+OF_T2, *OADJ2=gf+OF_OADJ2, *SS2=gf+OF_SS2, *XDS2=gf+OF_XDS2;
    float *SXA=gf+OF_SXA, *SXB=gf+OF_SXB, *SXC=gf+OF_SXC, *SXD=gf+OF_SXD, *SXE=gf+OF_SXE;
    float *SCORE=gf+OF_SCORE, *DEG=gf+OF_DEG, *DP=gf+OF_DP, *RS1=gf+OF_RS1, *RS2=gf+OF_RS2;
    float *SXS=gf+OF_SXS, *MEAN=gf+OF_MEAN, *XG=gf+OF_XG, *SXR=gf+OF_SXR;
    float *ST=gf+OF_ST, *PN=gf+OF_PN, *SAGG=gf+OF_SAGG;
    cudaStream_t sB = g_sB, sC = g_sC;

    // ---- CSR build (main stream) ----
    k_zeroi<<<256,256>>>(IO_DCNT, 65536);
    k_zerof<<<64,256>>>(SXS, 16384);
    k_count<<<2048,256>>>(src,dst);
    { dim3 g(32,2); k_scan_blk<<<g,256>>>(); }
    k_scan_top<<<1,64>>>();
    { dim3 g(32,2); k_scan_add<<<g,256>>>(); }
    k_fill<<<2048,256>>>(src,dst);
    k_sortl<<<256,256>>>();
    k_deg1<<<128,256>>>(DEG);
    k_pnorm<<<1,128>>>(pv1,PN+0);
    k_pnorm<<<1,128>>>(pv2,PN+1);
    k_pnorm<<<1,128>>>(pv3,PN+2);

    // ---- conv0 (fp32: feeds top-k scores) ----
    k_agg_w<<<4096,256>>>(x_in,nullptr,nullptr,src,AGGB,32768);
    gemm_f32_dual(0, AGGB,c0wr, x_in,c0wo, c0b, X0, 32768,128,128, 1);

    // ======== fork: sparse branch on sB ========
    cudaEventRecord(g_ev[0], 0);
    cudaStreamWaitEvent(sB, g_ev[0], 0);

    k_score<<<4096,256,0,sB>>>(X0,pv1,PN+0,SCORE,32768);
    k_topk<<<64,512,512*8,sB>>>(SCORE,512,256,IO_PL1);
    k_fillneg<<<128,256,0,sB>>>(IO_CM1,32768);
    k_mapset<<<64,256,0,sB>>>(IO_PL1,-1,IO_PO1,IO_CM1,16384);
    k_gate<<<16384,128,0,sB>>>(X0,SCORE,IO_PL1,SXA);
    k_readout<<<64,128,0,sB>>>(SXA,256,SXS);
    k_agg_w<<<2048,256,0,sB>>>(SXA,gi+IO_PO1,gi+IO_CM1,src,SAGG,16384);
    gemm_f32_dual(sB, SAGG,s2wr, SXA,s2wo, s2b, SXB, 16384,128,128, 1);
    k_score<<<2048,256,0,sB>>>(SXB,pv2,PN+1,SCORE,16384);
    k_topk<<<64,256,256*8,sB>>>(SCORE,256,128,IO_PL2);
    k_fillneg<<<128,256,0,sB>>>(IO_CM2,32768);
    k_mapset<<<32,256,0,sB>>>(IO_PL2,IO_PO1,IO_PO2,IO_CM2,8192);
    k_gate<<<8192,128,0,sB>>>(SXB,SCORE,IO_PL2,SXC);
    k_readout<<<64,128,0,sB>>>(SXC,128,SXS);
    k_agg_w<<<1024,256,0,sB>>>(SXC,gi+IO_PO2,gi+IO_CM2,src,SAGG,8192);
    gemm_f32_dual(sB, SAGG,s3wr, SXC,s3wo, s3b, SXD, 8192,128,128, 1);
    k_score<<<1024,256,0,sB>>>(SXD,pv3,PN+2,SCORE,8192);
    k_topk<<<64,128,128*8,sB>>>(SCORE,128,64,IO_PL3);
    k_gate<<<4096,128,0,sB>>>(SXD,SCORE,IO_PL3,SXE);
    k_readout<<<64,128,0,sB>>>(SXE,64,SXS);
    k_gemm64<<<dim3(2,1),256,0,sB>>>(SXS,l11w,l11b,SXR, 64,128,256, 1);
    cudaEventRecord(g_ev[1], sB);

    // ---- dense branch (main + sC overlap) ----
    gemm_tc(0,false,X0,p0w,p0b,nullptr,SBIG, 32768,256,128,0,0,0,1,0);
    k_softmax<<<32768,256,256*4>>>(SBIG,256);
    cudaEventRecord(g_ev[2], 0);

    // sC: T1 = adj@SBIG, then OADJ1 = SBIG^T @ T1
    cudaStreamWaitEvent(sC, g_ev[2], 0);
    k_adjs_w<<<4096,256,0,sC>>>(SBIG,dst,T1);
    gemm_tc(sC,true,SBIG,T1,nullptr,nullptr,OADJ1, 256,256,512, 131072,131072,65536,64,0);
    cudaEventRecord(g_ev[3], sC);

    // main: XD1, SS1 in parallel with sC
    gemm_tc(0,true,SBIG,X0,nullptr,nullptr,XD1, 256,128,512, 131072,65536,32768,64,0);
    gemm_tc(0,true,SBIG,SBIG,nullptr,nullptr,SS1, 256,256,512, 131072,131072,65536,64,0);
    cudaStreamWaitEvent(0, g_ev[3], 0);

    k_stats<<<64,256>>>(SBIG,OADJ1,SS1,DEG,512,256,ST+0,ST+64);
    k_adjp1<<<16384,256,256*4>>>(OADJ1,DP,256);
    k_adjp2<<<16384,256,256*4>>>(OADJ1,DP,RS1,256);

    // sage1 (rowscale fused via rsA)
    gemm_tc(0,false,OADJ1,XD1,nullptr,nullptr,AGGB, 256,128,256, 65536,32768,32768,64,0);
    gemm_tc_dual(AGGB,g1wr, XD1,g1wo, g1b, RS1, XDS1, 16384,128,128, 1);

    // pool1 assignment + mincut 2 (T2/OADJ2 chain on sC, XD2/SS2 on main)
    gemm_tc(0,false,XDS1,p1w,p1b,nullptr,S2, 16384,128,128,0,0,0,1,0);
    k_softmax<<<16384,128,128*4>>>(S2,128);
    cudaEventRecord(g_ev[4], 0);

    cudaStreamWaitEvent(sC, g_ev[4], 0);
    gemm_tc(sC,false,OADJ1,S2,nullptr,nullptr,T2, 256,128,256, 65536,32768,32768,64,0);
    gemm_tc(sC,true,S2,T2,nullptr,nullptr,OADJ2, 128,128,256, 32768,32768,16384,64,0);
    cudaEventRecord(g_ev[5], sC);

    gemm_tc(0,true,S2,XDS1,nullptr,nullptr,XD2, 128,128,256, 32768,32768,16384,64,0);
    gemm_tc(0,true,S2,S2,nullptr,nullptr,SS2, 128,128,256, 32768,32768,16384,64,0);
    cudaStreamWaitEvent(0, g_ev[5], 0);

    k_stats<<<64,256>>>(S2,OADJ2,SS2,RS1,256,128,ST+128,ST+192);
    k_adjp1<<<8192,128,128*4>>>(OADJ2,DP,128);
    k_adjp2<<<8192,128,128*4>>>(OADJ2,DP,RS2,128);

    // sage2 (rowscale fused)
    gemm_tc(0,false,OADJ2,XD2,nullptr,nullptr,AGGB, 128,128,128, 16384,16384,16384,64,0);
    gemm_tc_dual(AGGB,g2wr, XD2,g2wo, g2b, RS2, XDS2, 8192,128,128, 0);
    k_nodemean<<<64,128>>>(XDS2,MEAN);
    k_gemm64<<<dim3(2,1),256>>>(MEAN,l1w,l1b,XG, 64,128,128, 1);

    // ======== join sparse ========
    cudaStreamWaitEvent(0, g_ev[1], 0);

    // ---- heads ----
    k_lin2<<<1,640>>>(SXR,XG,l2w,l2b,out);
    k_final<<<1,64>>>(out,out_size);
}